// round 16
// baseline (speedup 1.0000x reference)
#include <cuda_runtime.h>
#include <cuda_fp16.h>
#include <stdint.h>

// Problem constants
#define BB 16
#define NN 8192
#define DD 256
#define HH 128
#define NP 64
#define KSEL 32
#define ROWS (BB * NN)          // 131072
#define SEL_PER_B (NP * KSEL)   // 2048
#define NPROD (ROWS / 128)      // 1024 producer blocks
#define NCONS (BB * NP)         // 1024 consumer blocks

#define LO_SCALE 256.0f
#define LO_INV   (1.0f / 256.0f)

// ---- fp16 pack helpers ----
__device__ __forceinline__ uint32_t pack_h2(float x, float y) {
    __half2 h = __floats2half2_rn(x, y);
    return *reinterpret_cast<uint32_t*>(&h);
}
__device__ __forceinline__ float2 unpack_h2(uint32_t u) {
    __half2 h = *reinterpret_cast<__half2*>(&u);
    return __half22float2(h);
}

__device__ __forceinline__ void mma_f16(float c[4],
                                        uint32_t a0, uint32_t a1, uint32_t a2, uint32_t a3,
                                        uint32_t b0, uint32_t b1) {
    asm volatile(
        "mma.sync.aligned.m16n8k16.row.col.f32.f16.f16.f32 "
        "{%0,%1,%2,%3}, {%4,%5,%6,%7}, {%8,%9}, {%0,%1,%2,%3};"
        : "+f"(c[0]), "+f"(c[1]), "+f"(c[2]), "+f"(c[3])
        : "r"(a0), "r"(a1), "r"(a2), "r"(a3), "r"(b0), "r"(b1));
}

__device__ __forceinline__ uint32_t smem_u32(const void* p) {
    uint32_t a;
    asm("{ .reg .u64 t; cvta.to.shared.u64 t, %1; cvt.u32.u64 %0, t; }" : "=r"(a) : "l"(p));
    return a;
}
__device__ __forceinline__ void cp_async16(uint32_t dst, const void* src) {
    asm volatile("cp.async.cg.shared.global [%0], [%1], 16;" :: "r"(dst), "l"(src));
}
__device__ __forceinline__ void cp_async8(uint32_t dst, const void* src) {
    asm volatile("cp.async.ca.shared.global [%0], [%1], 8;" :: "r"(dst), "l"(src));
}
#define CP_COMMIT() asm volatile("cp.async.commit_group;")
#define CP_WAIT0()  asm volatile("cp.async.wait_group 0;")

// W1 fragments table (written by producer blocks 0..63 at launch start)
__device__ uint4 g_Bf4[16][16][32];

// Cross-block sync state (reset by the last consumer each launch)
__device__ unsigned int g_prep_done = 0;           // -> 64
__device__ unsigned int g_batch_done[BB] = {};     // -> 64 each
__device__ unsigned int g_cons_done = 0;           // -> NCONS

#define ASTRIDE 18

__global__ __launch_bounds__(128, 2)
void k_fused(const float* __restrict__ features,
             const float* __restrict__ W1,
             const float* __restrict__ b1,
             const float* __restrict__ W2,
             const float* __restrict__ b2,
             const float* __restrict__ gumbel,
             const float* __restrict__ patches,
             float* __restrict__ logits,
             float* __restrict__ out_idx,
             float* __restrict__ out_sel)
{
    __shared__ float sA[2][128][ASTRIDE];
    __shared__ uint4 sB4[2][16][32];
    __shared__ float s_b1[HH], s_w2[HH];
    __shared__ float s_red[128][2];
    __shared__ int   s_idx[KSEL];

    const int bid  = blockIdx.x;
    const int tid  = threadIdx.x;
    const int wid  = tid >> 5;
    const int lane = tid & 31;

    if (bid < NPROD) {
        // ================= PRODUCER =================
        // Blocks 0..63: build W1 fragment table slice first.
        if (bid < 64) {
            int idx  = bid * 128 + tid;        // 0..8191
            int ln   = idx & 31;
            int nt   = (idx >> 5) & 15;
            int kt   = idx >> 9;
            int k0 = kt * 16 + (ln & 3) * 2;
            int n  = nt * 8 + (ln >> 2);
            uint32_t bh[2], bl[2];
#pragma unroll
            for (int r = 0; r < 2; r++) {
                int k = k0 + r * 8;
                float v0 = W1[(size_t)k * HH + n];
                float v1 = W1[(size_t)(k + 1) * HH + n];
                uint32_t h = pack_h2(v0, v1);
                float2 f = unpack_h2(h);
                bh[r] = h;
                bl[r] = pack_h2((v0 - f.x) * LO_SCALE, (v1 - f.y) * LO_SCALE);
            }
            g_Bf4[kt][nt][ln] = make_uint4(bh[0], bh[1], bl[0], bl[1]);
            __threadfence();
            __syncthreads();
            if (tid == 0) atomicAdd(&g_prep_done, 1u);
        }
        // All producers wait for the full fragment table.
        if (tid == 0) {
            volatile unsigned int* vp = &g_prep_done;
            while (*vp < 64u) __nanosleep(64);
        }
        __syncthreads();
        __threadfence();

        // ---- logits tile (round-12 config, unchanged math) ----
        const int wm   = wid >> 1;
        const int wn   = wid & 1;
        const int g    = lane >> 2;
        const int tig  = lane & 3;
        const int row0 = bid * 128;

        if (tid < HH) { s_b1[tid] = b1[tid]; s_w2[tid] = W2[tid]; }

        const float* Abase = features + (size_t)row0 * DD;

        auto prefetch = [&](int stage, int kt) {
            const int koff = kt * 16;
#pragma unroll
            for (int i = 0; i < 8; i++) {
                int cidx = tid + 128 * i;
                int r = cidx >> 3;
                int c = cidx & 7;
                cp_async8(smem_u32(&sA[stage][r][c * 2]),
                          Abase + (size_t)r * DD + koff + c * 2);
            }
            const char* src = (const char*)&g_Bf4[kt][0][0];
            uint32_t dst = smem_u32(&sB4[stage][0][0]);
#pragma unroll
            for (int i = 0; i < 4; i++) {
                int c = tid + 128 * i;
                cp_async16(dst + c * 16, src + c * 16);
            }
            CP_COMMIT();
        };

        prefetch(0, 0);

        float acc[4][8][4];
#pragma unroll
        for (int mt = 0; mt < 4; mt++)
#pragma unroll
            for (int nt = 0; nt < 8; nt++)
#pragma unroll
                for (int c = 0; c < 4; c++) acc[mt][nt][c] = 0.0f;

        const int rg = wm * 64 + g;
        const int kcol = tig * 2;

        for (int kt = 0; kt < 16; kt++) {
            const int buf = kt & 1;
            CP_WAIT0();
            __syncthreads();
            if (kt < 15) prefetch(buf ^ 1, kt + 1);

            uint4 bf[8];
#pragma unroll
            for (int nt = 0; nt < 8; nt++)
                bf[nt] = sB4[buf][wn * 8 + nt][lane];

            uint32_t Ah[4][4], Al[4][4], As[4][4];
#pragma unroll
            for (int mt = 0; mt < 4; mt++) {
                const int r0 = rg + mt * 16;
                float2 v00 = *(const float2*)&sA[buf][r0][kcol];
                float2 v10 = *(const float2*)&sA[buf][r0 + 8][kcol];
                float2 v01 = *(const float2*)&sA[buf][r0][kcol + 8];
                float2 v11 = *(const float2*)&sA[buf][r0 + 8][kcol + 8];
                Ah[mt][0] = pack_h2(v00.x, v00.y);
                Ah[mt][1] = pack_h2(v10.x, v10.y);
                Ah[mt][2] = pack_h2(v01.x, v01.y);
                Ah[mt][3] = pack_h2(v11.x, v11.y);
                float2 f;
                f = unpack_h2(Ah[mt][0]); Al[mt][0] = pack_h2(v00.x - f.x, v00.y - f.y);
                f = unpack_h2(Ah[mt][1]); Al[mt][1] = pack_h2(v10.x - f.x, v10.y - f.y);
                f = unpack_h2(Ah[mt][2]); Al[mt][2] = pack_h2(v01.x - f.x, v01.y - f.y);
                f = unpack_h2(Ah[mt][3]); Al[mt][3] = pack_h2(v11.x - f.x, v11.y - f.y);
                As[mt][0] = pack_h2(v00.x * LO_INV, v00.y * LO_INV);
                As[mt][1] = pack_h2(v10.x * LO_INV, v10.y * LO_INV);
                As[mt][2] = pack_h2(v01.x * LO_INV, v01.y * LO_INV);
                As[mt][3] = pack_h2(v11.x * LO_INV, v11.y * LO_INV);
            }

#pragma unroll
            for (int nt = 0; nt < 8; nt++)
#pragma unroll
                for (int mt = 0; mt < 4; mt++)
                    mma_f16(acc[mt][nt], Ah[mt][0], Ah[mt][1], Ah[mt][2], Ah[mt][3],
                            bf[nt].x, bf[nt].y);
#pragma unroll
            for (int nt = 0; nt < 8; nt++)
#pragma unroll
                for (int mt = 0; mt < 4; mt++)
                    mma_f16(acc[mt][nt], As[mt][0], As[mt][1], As[mt][2], As[mt][3],
                            bf[nt].z, bf[nt].w);
#pragma unroll
            for (int nt = 0; nt < 8; nt++)
#pragma unroll
                for (int mt = 0; mt < 4; mt++)
                    mma_f16(acc[mt][nt], Al[mt][0], Al[mt][1], Al[mt][2], Al[mt][3],
                            bf[nt].x, bf[nt].y);
        }

        float rs[8];
#pragma unroll
        for (int i = 0; i < 8; i++) rs[i] = 0.0f;
#pragma unroll
        for (int nt = 0; nt < 8; nt++) {
            const int c = wn * 64 + nt * 8 + tig * 2;
            float bb0 = s_b1[c],     w0 = s_w2[c];
            float bb1 = s_b1[c + 1], w1 = s_w2[c + 1];
#pragma unroll
            for (int mt = 0; mt < 4; mt++) {
                float x0 = acc[mt][nt][0] + bb0; x0 = x0 > 0.0f ? x0 : 0.0f;
                float x1 = acc[mt][nt][1] + bb1; x1 = x1 > 0.0f ? x1 : 0.0f;
                float x2 = acc[mt][nt][2] + bb0; x2 = x2 > 0.0f ? x2 : 0.0f;
                float x3 = acc[mt][nt][3] + bb1; x3 = x3 > 0.0f ? x3 : 0.0f;
                rs[2 * mt + 0] += x0 * w0 + x1 * w1;
                rs[2 * mt + 1] += x2 * w0 + x3 * w1;
            }
        }
#pragma unroll
        for (int off = 1; off <= 2; off <<= 1)
#pragma unroll
            for (int i = 0; i < 8; i++)
                rs[i] += __shfl_xor_sync(0xFFFFFFFFu, rs[i], off);

        if (tig == 0) {
#pragma unroll
            for (int mt = 0; mt < 4; mt++) {
                s_red[wm * 64 + mt * 16 + g][wn]     = rs[2 * mt + 0];
                s_red[wm * 64 + mt * 16 + g + 8][wn] = rs[2 * mt + 1];
            }
        }
        __syncthreads();
        logits[(size_t)row0 + tid] = s_red[tid][0] + s_red[tid][1] + __ldg(b2);

        // Signal tile completion for this batch.
        __threadfence();
        __syncthreads();
        if (tid == 0) atomicAdd(&g_batch_done[bid >> 6], 1u);

    } else {
        // ================= CONSUMER =================
        const int cid = bid - NPROD;
        const int b = cid >> 6;
        const int p = cid & 63;
        const float NEG_INF = __int_as_float(0xff800000);

        if (tid == 0) {
            volatile unsigned int* vb = &g_batch_done[b];
            while (*vb < 64u) __nanosleep(128);
        }
        __syncthreads();
        __threadfence();

        if (wid == 0) {
            float v[4];
            int nidx[4];
#pragma unroll
            for (int q = 0; q < 4; q++) {
                int n = p + 64 * (lane + 32 * q);
                size_t off = (size_t)b * NN + n;
                v[q] = __ldcg(&logits[off]) + gumbel[off];
                nidx[q] = n;
            }
            for (int it = 0; it < KSEL; it++) {
                float bv = v[0]; int bn = nidx[0];
#pragma unroll
                for (int q = 1; q < 4; q++)
                    if (v[q] > bv || (v[q] == bv && nidx[q] < bn)) { bv = v[q]; bn = nidx[q]; }
#pragma unroll
                for (int off = 16; off; off >>= 1) {
                    float ov = __shfl_xor_sync(0xFFFFFFFFu, bv, off);
                    int   on = __shfl_xor_sync(0xFFFFFFFFu, bn, off);
                    if (ov > bv || (ov == bv && on < bn)) { bv = ov; bn = on; }
                }
                if (lane == 0) {
                    s_idx[it] = bn;
                    out_idx[(size_t)b * SEL_PER_B + p * KSEL + it] = (float)bn;
                }
#pragma unroll
                for (int q = 0; q < 4; q++)
                    if (nidx[q] == bn) v[q] = NEG_INF;
            }
        }
        __syncthreads();

        // Copy the 32 selected rows; 4 warps x 8 rows.
#pragma unroll
        for (int r = wid; r < KSEL; r += 4) {
            const int n = s_idx[r];
            const float4* src = (const float4*)&patches[((size_t)b * NN + n) * DD];
            float4* dst = (float4*)&out_sel[((size_t)b * SEL_PER_B + p * KSEL + r) * DD];
            dst[lane]      = src[lane];
            dst[lane + 32] = src[lane + 32];
        }

        // Last consumer resets sync state for the next graph replay.
        __syncthreads();
        if (tid == 0) {
            unsigned int done = atomicAdd(&g_cons_done, 1u);
            if (done == NCONS - 1) {
                g_prep_done = 0;
                g_cons_done = 0;
#pragma unroll
                for (int i = 0; i < BB; i++) g_batch_done[i] = 0;
                __threadfence();
            }
        }
    }
}

// ============================================================
// launch
// ============================================================
extern "C" void kernel_launch(void* const* d_in, const int* in_sizes, int n_in,
                              void* d_out, int out_size)
{
    const float* patches  = (const float*)d_in[0];
    const float* features = (const float*)d_in[1];
    const float* W1       = (const float*)d_in[2];
    const float* b1       = (const float*)d_in[3];
    const float* W2       = (const float*)d_in[4];
    const float* b2       = (const float*)d_in[5];
    const float* gumbel   = (const float*)d_in[6];

    float* out      = (float*)d_out;
    float* out_sel  = out;                                 // [B, 2048, 256]
    float* out_idx  = out + (size_t)BB * SEL_PER_B * DD;   // [B, 2048]
    float* out_log  = out_idx + (size_t)BB * SEL_PER_B;    // [B, N]

    k_fused<<<NPROD + NCONS, 128>>>(features, W1, b1, W2, b2, gumbel,
                                    patches, out_log, out_idx, out_sel);
}

// round 17
// speedup vs baseline: 1.1291x; 1.1291x over previous
#include <cuda_runtime.h>
#include <cuda_fp16.h>
#include <stdint.h>

// Problem constants
#define BB 16
#define NN 8192
#define DD 256
#define HH 128
#define NP 64
#define KSEL 32
#define ROWS (BB * NN)          // 131072
#define SEL_PER_B (NP * KSEL)   // 2048
#define TROWS 64                // rows per CTA tile
#define NTILES (ROWS / TROWS)   // 2048

#define LO_SCALE 256.0f         // 2^8: B residual plane scale
#define LO_INV   (1.0f / 256.0f)

// ---- fp16 pack helpers ----
__device__ __forceinline__ uint32_t pack_h2(float x, float y) {
    __half2 h = __floats2half2_rn(x, y);
    return *reinterpret_cast<uint32_t*>(&h);
}
__device__ __forceinline__ float2 unpack_h2(uint32_t u) {
    __half2 h = *reinterpret_cast<__half2*>(&u);
    return __half22float2(h);
}

__device__ __forceinline__ void mma_f16(float c[4],
                                        uint32_t a0, uint32_t a1, uint32_t a2, uint32_t a3,
                                        uint32_t b0, uint32_t b1) {
    asm volatile(
        "mma.sync.aligned.m16n8k16.row.col.f32.f16.f16.f32 "
        "{%0,%1,%2,%3}, {%4,%5,%6,%7}, {%8,%9}, {%0,%1,%2,%3};"
        : "+f"(c[0]), "+f"(c[1]), "+f"(c[2]), "+f"(c[3])
        : "r"(a0), "r"(a1), "r"(a2), "r"(a3), "r"(b0), "r"(b1));
}

__device__ __forceinline__ uint32_t smem_u32(const void* p) {
    uint32_t a;
    asm("{ .reg .u64 t; cvta.to.shared.u64 t, %1; cvt.u32.u64 %0, t; }" : "=r"(a) : "l"(p));
    return a;
}
__device__ __forceinline__ void cp_async16(uint32_t dst, const void* src) {
    asm volatile("cp.async.cg.shared.global [%0], [%1], 16;" :: "r"(dst), "l"(src));
}
__device__ __forceinline__ void cp_async8(uint32_t dst, const void* src) {
    asm volatile("cp.async.ca.shared.global [%0], [%1], 8;" :: "r"(dst), "l"(src));
}
#define CP_COMMIT() asm volatile("cp.async.commit_group;")
#define CP_WAIT0()  asm volatile("cp.async.wait_group 0;")

// W1 fragments, one uint4 per (kt, nt, lane)
__device__ uint4 g_Bf4[16][16][32];

// ============================================================
// K0: build W1 fragment table
// ============================================================
__global__ void k_prepB(const float* __restrict__ W1)
{
    int idx  = blockIdx.x * 256 + threadIdx.x;   // 0..8191
    int lane = idx & 31;
    int nt   = (idx >> 5) & 15;
    int kt   = idx >> 9;

    int k0 = kt * 16 + (lane & 3) * 2;
    int n  = nt * 8 + (lane >> 2);

    uint32_t bh[2], bl[2];
#pragma unroll
    for (int r = 0; r < 2; r++) {
        int k = k0 + r * 8;
        float v0 = W1[(size_t)k * HH + n];
        float v1 = W1[(size_t)(k + 1) * HH + n];
        uint32_t h = pack_h2(v0, v1);
        float2 f = unpack_h2(h);
        bh[r] = h;
        bl[r] = pack_h2((v0 - f.x) * LO_SCALE, (v1 - f.y) * LO_SCALE);
    }
    g_Bf4[kt][nt][lane] = make_uint4(bh[0], bh[1], bl[0], bl[1]);
}

// ============================================================
// K1: logits = relu(features @ W1 + b1) @ W2 + b2
// fp16 3-product fold-free split. CTA: 64 rows x 128 cols,
// 128 threads, 4 warps (2wm x 2wn), warp tile 32x64, mt=2.
// __launch_bounds__(128,3): 3 CTAs/SM -> 12 warps/SM to cover
// per-warp dependency bubbles (tensor pipe measured 38% busy).
// ============================================================
#define ASTRIDE 18

__global__ __launch_bounds__(128, 3)
void k_logits_tc(const float* __restrict__ features,
                 const float* __restrict__ b1,
                 const float* __restrict__ W2,
                 const float* __restrict__ b2,
                 float* __restrict__ logits)
{
    __shared__ float sA[2][TROWS][ASTRIDE];
    __shared__ uint4 sB4[2][16][32];
    __shared__ float s_b1[HH], s_w2[HH];
    __shared__ float s_red[TROWS][2];

    const int tid  = threadIdx.x;
    const int wid  = tid >> 5;
    const int lane = tid & 31;
    const int wm   = wid >> 1;       // 0..1 (row half of 64)
    const int wn   = wid & 1;        // 0..1 (col half of 128)
    const int g    = lane >> 2;
    const int tig  = lane & 3;
    const int row0 = blockIdx.x * TROWS;

    if (tid < HH) { s_b1[tid] = b1[tid]; s_w2[tid] = W2[tid]; }

    const float* Abase = features + (size_t)row0 * DD;

    auto prefetch = [&](int stage, int kt) {
        const int koff = kt * 16;
        // A slab: 64 rows x 16 floats = 512 8B chunks
#pragma unroll
        for (int i = 0; i < 4; i++) {
            int cidx = tid + 128 * i;
            int r = cidx >> 3;
            int c = cidx & 7;
            cp_async8(smem_u32(&sA[stage][r][c * 2]),
                      Abase + (size_t)r * DD + koff + c * 2);
        }
        // B slab: 8 KB = 512 16B chunks
        const char* src = (const char*)&g_Bf4[kt][0][0];
        uint32_t dst = smem_u32(&sB4[stage][0][0]);
#pragma unroll
        for (int i = 0; i < 4; i++) {
            int c = tid + 128 * i;
            cp_async16(dst + c * 16, src + c * 16);
        }
        CP_COMMIT();
    };

    prefetch(0, 0);

    float acc[2][8][4];
#pragma unroll
    for (int mt = 0; mt < 2; mt++)
#pragma unroll
        for (int nt = 0; nt < 8; nt++)
#pragma unroll
            for (int c = 0; c < 4; c++) acc[mt][nt][c] = 0.0f;

    const int rg = wm * 32 + g;
    const int kcol = tig * 2;

    for (int kt = 0; kt < 16; kt++) {
        const int buf = kt & 1;
        CP_WAIT0();
        __syncthreads();
        if (kt < 15) prefetch(buf ^ 1, kt + 1);

        // B fragments: one LDS.128 per nt
        uint4 bf[8];
#pragma unroll
        for (int nt = 0; nt < 8; nt++)
            bf[nt] = sB4[buf][wn * 8 + nt][lane];

        // A fragments: hi, residual, hi scaled by 2^-8
        uint32_t Ah[2][4], Al[2][4], As[2][4];
#pragma unroll
        for (int mt = 0; mt < 2; mt++) {
            const int r0 = rg + mt * 16;
            float2 v00 = *(const float2*)&sA[buf][r0][kcol];
            float2 v10 = *(const float2*)&sA[buf][r0 + 8][kcol];
            float2 v01 = *(const float2*)&sA[buf][r0][kcol + 8];
            float2 v11 = *(const float2*)&sA[buf][r0 + 8][kcol + 8];
            Ah[mt][0] = pack_h2(v00.x, v00.y);
            Ah[mt][1] = pack_h2(v10.x, v10.y);
            Ah[mt][2] = pack_h2(v01.x, v01.y);
            Ah[mt][3] = pack_h2(v11.x, v11.y);
            float2 f;
            f = unpack_h2(Ah[mt][0]); Al[mt][0] = pack_h2(v00.x - f.x, v00.y - f.y);
            f = unpack_h2(Ah[mt][1]); Al[mt][1] = pack_h2(v10.x - f.x, v10.y - f.y);
            f = unpack_h2(Ah[mt][2]); Al[mt][2] = pack_h2(v01.x - f.x, v01.y - f.y);
            f = unpack_h2(Ah[mt][3]); Al[mt][3] = pack_h2(v11.x - f.x, v11.y - f.y);
            As[mt][0] = pack_h2(v00.x * LO_INV, v00.y * LO_INV);
            As[mt][1] = pack_h2(v10.x * LO_INV, v10.y * LO_INV);
            As[mt][2] = pack_h2(v01.x * LO_INV, v01.y * LO_INV);
            As[mt][3] = pack_h2(v11.x * LO_INV, v11.y * LO_INV);
        }

        // 3 product passes, 16 independent MMAs each
#pragma unroll
        for (int nt = 0; nt < 8; nt++)
#pragma unroll
            for (int mt = 0; mt < 2; mt++)
                mma_f16(acc[mt][nt], Ah[mt][0], Ah[mt][1], Ah[mt][2], Ah[mt][3],
                        bf[nt].x, bf[nt].y);
#pragma unroll
        for (int nt = 0; nt < 8; nt++)
#pragma unroll
            for (int mt = 0; mt < 2; mt++)
                mma_f16(acc[mt][nt], As[mt][0], As[mt][1], As[mt][2], As[mt][3],
                        bf[nt].z, bf[nt].w);
#pragma unroll
        for (int nt = 0; nt < 8; nt++)
#pragma unroll
            for (int mt = 0; mt < 2; mt++)
                mma_f16(acc[mt][nt], Al[mt][0], Al[mt][1], Al[mt][2], Al[mt][3],
                        bf[nt].x, bf[nt].y);
    }

    // Epilogue: relu(acc + b1) * W2, reduce over hidden
    float rs[4];
#pragma unroll
    for (int i = 0; i < 4; i++) rs[i] = 0.0f;
#pragma unroll
    for (int nt = 0; nt < 8; nt++) {
        const int c = wn * 64 + nt * 8 + tig * 2;
        float bb0 = s_b1[c],     w0 = s_w2[c];
        float bb1 = s_b1[c + 1], w1 = s_w2[c + 1];
#pragma unroll
        for (int mt = 0; mt < 2; mt++) {
            float x0 = acc[mt][nt][0] + bb0; x0 = x0 > 0.0f ? x0 : 0.0f;
            float x1 = acc[mt][nt][1] + bb1; x1 = x1 > 0.0f ? x1 : 0.0f;
            float x2 = acc[mt][nt][2] + bb0; x2 = x2 > 0.0f ? x2 : 0.0f;
            float x3 = acc[mt][nt][3] + bb1; x3 = x3 > 0.0f ? x3 : 0.0f;
            rs[2 * mt + 0] += x0 * w0 + x1 * w1;
            rs[2 * mt + 1] += x2 * w0 + x3 * w1;
        }
    }
#pragma unroll
    for (int off = 1; off <= 2; off <<= 1)
#pragma unroll
        for (int i = 0; i < 4; i++)
            rs[i] += __shfl_xor_sync(0xFFFFFFFFu, rs[i], off);

    if (tig == 0) {
#pragma unroll
        for (int mt = 0; mt < 2; mt++) {
            s_red[wm * 32 + mt * 16 + g][wn]     = rs[2 * mt + 0];
            s_red[wm * 32 + mt * 16 + g + 8][wn] = rs[2 * mt + 1];
        }
    }
    __syncthreads();
    if (tid < TROWS)
        logits[(size_t)row0 + tid] = s_red[tid][0] + s_red[tid][1] + __ldg(b2);
}

// ============================================================
// K2: FUSED select + gather. One block per (batch, parcel).
// ============================================================
__global__ __launch_bounds__(256)
void k_selgather(const float* __restrict__ logits,
                 const float* __restrict__ gumbel,
                 const float* __restrict__ patches,
                 float* __restrict__ out_idx,
                 float* __restrict__ out_sel)
{
    __shared__ int s_idx[KSEL];

    const int b = blockIdx.x >> 6;
    const int p = blockIdx.x & 63;
    const int wid  = threadIdx.x >> 5;
    const int lane = threadIdx.x & 31;
    const float NEG_INF = __int_as_float(0xff800000);

    if (wid == 0) {
        float v[4];
        int nidx[4];
#pragma unroll
        for (int q = 0; q < 4; q++) {
            int n = p + 64 * (lane + 32 * q);
            size_t off = (size_t)b * NN + n;
            v[q] = logits[off] + gumbel[off];
            nidx[q] = n;
        }
        for (int it = 0; it < KSEL; it++) {
            float bv = v[0]; int bn = nidx[0];
#pragma unroll
            for (int q = 1; q < 4; q++)
                if (v[q] > bv || (v[q] == bv && nidx[q] < bn)) { bv = v[q]; bn = nidx[q]; }
#pragma unroll
            for (int off = 16; off; off >>= 1) {
                float ov = __shfl_xor_sync(0xFFFFFFFFu, bv, off);
                int   on = __shfl_xor_sync(0xFFFFFFFFu, bn, off);
                if (ov > bv || (ov == bv && on < bn)) { bv = ov; bn = on; }
            }
            if (lane == 0) {
                s_idx[it] = bn;
                out_idx[(size_t)b * SEL_PER_B + p * KSEL + it] = (float)bn;
            }
#pragma unroll
            for (int q = 0; q < 4; q++)
                if (nidx[q] == bn) v[q] = NEG_INF;
        }
    }
    __syncthreads();

#pragma unroll
    for (int r = wid; r < KSEL; r += 8) {
        const int n = s_idx[r];
        const float4* src = (const float4*)&patches[((size_t)b * NN + n) * DD];
        float4* dst = (float4*)&out_sel[((size_t)b * SEL_PER_B + p * KSEL + r) * DD];
        dst[lane]      = src[lane];
        dst[lane + 32] = src[lane + 32];
    }
}

// ============================================================
// launch
// ============================================================
extern "C" void kernel_launch(void* const* d_in, const int* in_sizes, int n_in,
                              void* d_out, int out_size)
{
    const float* patches  = (const float*)d_in[0];
    const float* features = (const float*)d_in[1];
    const float* W1       = (const float*)d_in[2];
    const float* b1       = (const float*)d_in[3];
    const float* W2       = (const float*)d_in[4];
    const float* b2       = (const float*)d_in[5];
    const float* gumbel   = (const float*)d_in[6];

    float* out      = (float*)d_out;
    float* out_sel  = out;                                 // [B, 2048, 256]
    float* out_idx  = out + (size_t)BB * SEL_PER_B * DD;   // [B, 2048]
    float* out_log  = out_idx + (size_t)BB * SEL_PER_B;    // [B, N]

    k_prepB<<<32, 256>>>(W1);
    k_logits_tc<<<NTILES, 128>>>(features, b1, W2, b2, out_log);
    k_selgather<<<BB * NP, 256>>>(out_log, gumbel, patches, out_idx, out_sel);
}